// round 4
// baseline (speedup 1.0000x reference)
#include <cuda_runtime.h>
#include <cstdint>

#define HDIM 128
#define MAXN 65536
#define MAXE 2200000

// Scratch (allocation-free rule: static __device__ arrays)
__device__ __align__(16) float g_buf0[(size_t)MAXN * HDIM];
__device__ __align__(16) float g_buf1[(size_t)MAXN * HDIM];
__device__ float g_dis[MAXN];
__device__ int   g_deg2[MAXN];      // in-degree (edges only)
__device__ int   g_cur[MAXN];       // fill cursor
__device__ int   g_off[MAXN + 1];   // CSR offsets (by dst)
__device__ int   g_csr[MAXE];       // CSR: src node per edge slot
__device__ int   g_bsum[64];        // scan block sums
__device__ int   g_bpre[64];        // scan block prefixes
__device__ int   g_is64;            // edge_index dtype flag

// ---------------- dtype probe ----------------
__global__ void k_detect(const void* __restrict__ ei, int E, int N) {
    if (threadIdx.x != 0 || blockIdx.x != 0) return;
    const long long* p = (const long long*)ei;
    int is64 = 1;
    int n = E < 64 ? E : 64;
    for (int i = 0; i < n; i++) {
        long long v = p[i];
        if (v < 0 || v >= (long long)N) { is64 = 0; break; }
    }
    g_is64 = is64;
}

__device__ __forceinline__ int load_idx(const void* __restrict__ ei, size_t pos) {
    return g_is64 ? (int)((const long long*)ei)[pos]
                  : ((const int*)ei)[pos];
}

// ---------------- degree ----------------
__global__ void k_init(int N) {
    int i = blockIdx.x * blockDim.x + threadIdx.x;
    if (i < N) { g_deg2[i] = 0; g_cur[i] = 0; }
}

__global__ void k_count(const void* __restrict__ ei, int E, int N) {
    int e = blockIdx.x * blockDim.x + threadIdx.x;
    if (e >= E) return;
    int d = load_idx(ei, (size_t)E + e);
    if ((unsigned)d < (unsigned)N) atomicAdd(&g_deg2[d], 1);
}

__global__ void k_dis(int N) {
    int i = blockIdx.x * blockDim.x + threadIdx.x;
    if (i < N) g_dis[i] = rsqrtf((float)(1 + g_deg2[i]));
}

// ---------------- exclusive scan of g_deg2 -> g_off ----------------
// scan1: block of 256 threads covers 1024 elements (4/thread)
__global__ __launch_bounds__(256) void k_scan1(int N) {
    __shared__ int ssum[256];
    int base = blockIdx.x * 1024 + threadIdx.x * 4;
    int v0 = 0, v1 = 0, v2 = 0, v3 = 0;
    if (base + 0 < N) v0 = g_deg2[base + 0];
    if (base + 1 < N) v1 = g_deg2[base + 1];
    if (base + 2 < N) v2 = g_deg2[base + 2];
    if (base + 3 < N) v3 = g_deg2[base + 3];
    int t = v0 + v1 + v2 + v3;
    ssum[threadIdx.x] = t;
    __syncthreads();
    for (int d = 1; d < 256; d <<= 1) {
        int x = (threadIdx.x >= d) ? ssum[threadIdx.x - d] : 0;
        __syncthreads();
        ssum[threadIdx.x] += x;
        __syncthreads();
    }
    int excl = ssum[threadIdx.x] - t;
    if (base + 0 < N) g_off[base + 0] = excl;
    if (base + 1 < N) g_off[base + 1] = excl + v0;
    if (base + 2 < N) g_off[base + 2] = excl + v0 + v1;
    if (base + 3 < N) g_off[base + 3] = excl + v0 + v1 + v2;
    if (threadIdx.x == 255) g_bsum[blockIdx.x] = ssum[255];
}

__global__ void k_scan2(int nb) {
    if (threadIdx.x == 0 && blockIdx.x == 0) {
        int run = 0;
        for (int i = 0; i < nb; i++) { g_bpre[i] = run; run += g_bsum[i]; }
    }
}

__global__ void k_scan3(int N, int E) {
    int i = blockIdx.x * blockDim.x + threadIdx.x;
    if (i < N) g_off[i] += g_bpre[i >> 10];
    if (i == 0) g_off[N] = E;
}

// ---------------- CSR fill ----------------
__global__ void k_fill(const void* __restrict__ ei, int E, int N) {
    int e = blockIdx.x * blockDim.x + threadIdx.x;
    if (e >= E) return;
    int s = load_idx(ei, e);
    int d = load_idx(ei, (size_t)E + e);
    if ((unsigned)d >= (unsigned)N) return;
    if ((unsigned)s >= (unsigned)N) s = 0;  // clamp (shouldn't happen)
    int pos = atomicAdd(&g_cur[d], 1);
    g_csr[g_off[d] + pos] = s;
}

// ---------------- GEMM: hs = (X @ W) * dis[row] -> OUT ----------------
__global__ __launch_bounds__(256) void k_gemm_scale(
    const float* __restrict__ X, const float* __restrict__ W,
    float* __restrict__ OUT, int N)
{
    __shared__ float sA[64][HDIM];

    int tx = threadIdx.x & 31;
    int ty = threadIdx.x >> 5;
    int rowBase = blockIdx.x * 64;

    for (int t = threadIdx.x; t < 64 * (HDIM / 4); t += 256) {
        int r  = t >> 5;
        int c4 = t & 31;
        int row = rowBase + r;
        float4 v = make_float4(0.f, 0.f, 0.f, 0.f);
        if (row < N) v = *(const float4*)(X + (size_t)row * HDIM + c4 * 4);
        *(float4*)(&sA[r][c4 * 4]) = v;
    }
    __syncthreads();

    float acc[8][4];
    #pragma unroll
    for (int i = 0; i < 8; i++)
        #pragma unroll
        for (int c = 0; c < 4; c++) acc[i][c] = 0.f;

    #pragma unroll 4
    for (int k = 0; k < HDIM; k++) {
        float4 w = __ldg((const float4*)(W + (size_t)k * HDIM + tx * 4));
        #pragma unroll
        for (int i = 0; i < 8; i++) {
            float a = sA[ty * 8 + i][k];
            acc[i][0] = fmaf(a, w.x, acc[i][0]);
            acc[i][1] = fmaf(a, w.y, acc[i][1]);
            acc[i][2] = fmaf(a, w.z, acc[i][2]);
            acc[i][3] = fmaf(a, w.w, acc[i][3]);
        }
    }

    #pragma unroll
    for (int i = 0; i < 8; i++) {
        int row = rowBase + ty * 8 + i;
        if (row < N) {
            float s = g_dis[row];
            float4 v = make_float4(acc[i][0] * s, acc[i][1] * s,
                                   acc[i][2] * s, acc[i][3] * s);
            *(float4*)(OUT + (size_t)row * HDIM + tx * 4) = v;
        }
    }
}

// ---------------- gather + finalize ----------------
// One warp per node. acc init = hs[node] (self loop).
// out[node] = relu(dis[node] * (hs[node] + sum_in hs[src]) + b)
__global__ __launch_bounds__(256) void k_gather(
    const float* __restrict__ hs, float* __restrict__ out,
    const float* __restrict__ bias, int N)
{
    int node = blockIdx.x * 8 + (threadIdx.x >> 5);
    if (node >= N) return;
    int lane = threadIdx.x & 31;

    float4 acc = *(const float4*)(hs + (size_t)node * HDIM + lane * 4);
    int beg = g_off[node], end = g_off[node + 1];

    for (int base = beg; base < end; base += 32) {
        int n = end - base; if (n > 32) n = 32;
        int eid = (lane < n) ? g_csr[base + lane] : 0;
        #pragma unroll 4
        for (int j = 0; j < n; j++) {
            int s = __shfl_sync(0xffffffffu, eid, j);
            float4 v = __ldg((const float4*)(hs + (size_t)s * HDIM + lane * 4));
            acc.x += v.x; acc.y += v.y; acc.z += v.z; acc.w += v.w;
        }
    }

    float sc = g_dis[node];
    float4 bb = __ldg((const float4*)(bias + lane * 4));
    float4 r;
    r.x = fmaxf(fmaf(sc, acc.x, bb.x), 0.f);
    r.y = fmaxf(fmaf(sc, acc.y, bb.y), 0.f);
    r.z = fmaxf(fmaf(sc, acc.z, bb.z), 0.f);
    r.w = fmaxf(fmaf(sc, acc.w, bb.w), 0.f);
    *(float4*)(out + (size_t)node * HDIM + lane * 4) = r;
}

extern "C" void kernel_launch(void* const* d_in, const int* in_sizes, int n_in,
                              void* d_out, int out_size)
{
    const float* x  = (const float*)d_in[0];
    const void*  ei = d_in[1];
    const float* W1 = (const float*)d_in[2];
    const float* b1 = (const float*)d_in[3];
    const float* W2 = (const float*)d_in[4];
    const float* b2 = (const float*)d_in[5];

    int H = in_sizes[3];
    int D = in_sizes[2] / H;
    int N = in_sizes[0] / D;
    int E = in_sizes[1] / 2;
    (void)D; (void)n_in; (void)out_size;

    int nb  = (N + 1023) / 1024;        // scan blocks
    int eb  = (E + 255) / 256;
    int nb256 = (N + 255) / 256;

    // probe + degree + normalization + CSR build
    k_detect<<<1, 32>>>(ei, E, N);
    k_init<<<nb256, 256>>>(N);
    k_count<<<eb, 256>>>(ei, E, N);
    k_dis<<<nb256, 256>>>(N);
    k_scan1<<<nb, 256>>>(N);
    k_scan2<<<1, 32>>>(nb);
    k_scan3<<<nb256, 256>>>(N, E);
    k_fill<<<eb, 256>>>(ei, E, N);

    int gemmBlocks = (N + 63) / 64;
    int gathBlocks = (N + 7) / 8;

    // layer 1: hs -> buf0, gathered z -> buf1
    k_gemm_scale<<<gemmBlocks, 256>>>(x, W1, g_buf0, N);
    k_gather<<<gathBlocks, 256>>>(g_buf0, g_buf1, b1, N);

    // layer 2: hs -> buf0, gathered z -> d_out
    k_gemm_scale<<<gemmBlocks, 256>>>(g_buf1, W2, g_buf0, N);
    k_gather<<<gathBlocks, 256>>>(g_buf0, (float*)d_out, b2, N);
}

// round 5
// speedup vs baseline: 36.2223x; 36.2223x over previous
#include <cuda_runtime.h>
#include <cstdint>

#define HDIM 128
#define MAXN 65536
#define MAXE 2200000

// Scratch (allocation-free rule: static __device__ arrays).
// NEVER referenced from host code — device-side selection only.
__device__ __align__(16) float g_buf0[(size_t)MAXN * HDIM]; // hs (gemm out)
__device__ __align__(16) float g_buf1[(size_t)MAXN * HDIM]; // layer-1 activations
__device__ float g_dis[MAXN];
__device__ int   g_deg2[MAXN];      // in-degree (edges only)
__device__ int   g_cur[MAXN];       // fill cursor
__device__ int   g_off[MAXN + 1];   // CSR offsets (by dst)
__device__ int   g_csr[MAXE];       // CSR: src node per edge slot
__device__ int   g_bsum[64];        // scan block sums
__device__ int   g_bpre[64];        // scan block prefixes
__device__ int   g_is64;            // edge_index dtype flag

// ---------------- dtype probe (warp-parallel) ----------------
// Lane i reads entry i as int64; all-in-range => int64. For int32 data the
// reinterpreted pairs are ~uniform in [0,2^63) so P(false int64) ~ 0.
__global__ void k_detect(const void* __restrict__ ei, int E, int N) {
    if (blockIdx.x != 0) return;
    int lane = threadIdx.x & 31;
    const long long* p = (const long long*)ei;
    int n = E < 32 ? E : 32;
    long long v = (lane < n) ? p[lane] : 0;
    bool ok = (v >= 0 && v < (long long)N);
    unsigned m = __ballot_sync(0xffffffffu, ok);
    if (threadIdx.x == 0) g_is64 = (m == 0xffffffffu) ? 1 : 0;
}

__device__ __forceinline__ int load_idx(const void* __restrict__ ei, size_t pos) {
    return g_is64 ? (int)((const long long*)ei)[pos]
                  : ((const int*)ei)[pos];
}

// ---------------- degree ----------------
__global__ void k_init(int N) {
    int i = blockIdx.x * blockDim.x + threadIdx.x;
    if (i < N) { g_deg2[i] = 0; g_cur[i] = 0; }
}

__global__ void k_count(const void* __restrict__ ei, int E, int N) {
    int e = blockIdx.x * blockDim.x + threadIdx.x;
    if (e >= E) return;
    int d = load_idx(ei, (size_t)E + e);
    if ((unsigned)d < (unsigned)N) atomicAdd(&g_deg2[d], 1);
}

__global__ void k_dis(int N) {
    int i = blockIdx.x * blockDim.x + threadIdx.x;
    if (i < N) g_dis[i] = rsqrtf((float)(1 + g_deg2[i]));
}

// ---------------- exclusive scan of g_deg2 -> g_off ----------------
__global__ __launch_bounds__(256) void k_scan1(int N) {
    __shared__ int ssum[256];
    int base = blockIdx.x * 1024 + threadIdx.x * 4;
    int v0 = 0, v1 = 0, v2 = 0, v3 = 0;
    if (base + 0 < N) v0 = g_deg2[base + 0];
    if (base + 1 < N) v1 = g_deg2[base + 1];
    if (base + 2 < N) v2 = g_deg2[base + 2];
    if (base + 3 < N) v3 = g_deg2[base + 3];
    int t = v0 + v1 + v2 + v3;
    ssum[threadIdx.x] = t;
    __syncthreads();
    for (int d = 1; d < 256; d <<= 1) {
        int x = (threadIdx.x >= d) ? ssum[threadIdx.x - d] : 0;
        __syncthreads();
        ssum[threadIdx.x] += x;
        __syncthreads();
    }
    int excl = ssum[threadIdx.x] - t;
    if (base + 0 < N) g_off[base + 0] = excl;
    if (base + 1 < N) g_off[base + 1] = excl + v0;
    if (base + 2 < N) g_off[base + 2] = excl + v0 + v1;
    if (base + 3 < N) g_off[base + 3] = excl + v0 + v1 + v2;
    if (threadIdx.x == 255) g_bsum[blockIdx.x] = ssum[255];
}

// 64-wide scan of block sums (2 warps, smem Hillis-Steele)
__global__ void k_scan2(int nb) {
    __shared__ int s[64];
    int i = threadIdx.x;
    int v = (i < nb) ? g_bsum[i] : 0;
    s[i] = v;
    __syncthreads();
    for (int d = 1; d < 64; d <<= 1) {
        int x = (i >= d) ? s[i - d] : 0;
        __syncthreads();
        s[i] += x;
        __syncthreads();
    }
    if (i < nb) g_bpre[i] = s[i] - v;   // exclusive
}

__global__ void k_scan3(int N, int E) {
    int i = blockIdx.x * blockDim.x + threadIdx.x;
    if (i < N) g_off[i] += g_bpre[i >> 10];
    if (i == 0) g_off[N] = E;
}

// ---------------- CSR fill ----------------
__global__ void k_fill(const void* __restrict__ ei, int E, int N) {
    int e = blockIdx.x * blockDim.x + threadIdx.x;
    if (e >= E) return;
    int s = load_idx(ei, e);
    int d = load_idx(ei, (size_t)E + e);
    if ((unsigned)d >= (unsigned)N) return;
    if ((unsigned)s >= (unsigned)N) s = 0;
    int pos = atomicAdd(&g_cur[d], 1);
    g_csr[g_off[d] + pos] = s;
}

// ---------------- GEMM: hs = (X @ W) * dis[row] -> g_buf0 ----------------
// srcSel: 0 = external X, 1 = g_buf1. Output always g_buf0.
__global__ __launch_bounds__(256) void k_gemm_scale(
    const float* __restrict__ Xext, const float* __restrict__ W,
    int N, int srcSel)
{
    __shared__ float sA[64][HDIM];
    const float* __restrict__ X = srcSel ? g_buf1 : Xext;

    int tx = threadIdx.x & 31;
    int ty = threadIdx.x >> 5;
    int rowBase = blockIdx.x * 64;

    for (int t = threadIdx.x; t < 64 * (HDIM / 4); t += 256) {
        int r  = t >> 5;
        int c4 = t & 31;
        int row = rowBase + r;
        float4 v = make_float4(0.f, 0.f, 0.f, 0.f);
        if (row < N) v = *(const float4*)(X + (size_t)row * HDIM + c4 * 4);
        *(float4*)(&sA[r][c4 * 4]) = v;
    }
    __syncthreads();

    float acc[8][4];
    #pragma unroll
    for (int i = 0; i < 8; i++)
        #pragma unroll
        for (int c = 0; c < 4; c++) acc[i][c] = 0.f;

    #pragma unroll 4
    for (int k = 0; k < HDIM; k++) {
        float4 w = __ldg((const float4*)(W + (size_t)k * HDIM + tx * 4));
        #pragma unroll
        for (int i = 0; i < 8; i++) {
            float a = sA[ty * 8 + i][k];
            acc[i][0] = fmaf(a, w.x, acc[i][0]);
            acc[i][1] = fmaf(a, w.y, acc[i][1]);
            acc[i][2] = fmaf(a, w.z, acc[i][2]);
            acc[i][3] = fmaf(a, w.w, acc[i][3]);
        }
    }

    #pragma unroll
    for (int i = 0; i < 8; i++) {
        int row = rowBase + ty * 8 + i;
        if (row < N) {
            float s = g_dis[row];
            float4 v = make_float4(acc[i][0] * s, acc[i][1] * s,
                                   acc[i][2] * s, acc[i][3] * s);
            *(float4*)(g_buf0 + (size_t)row * HDIM + tx * 4) = v;
        }
    }
}

// ---------------- gather + finalize ----------------
// One warp per node, hs = g_buf0. acc init = hs[node] (self loop).
// out[node] = relu(dis[node] * (hs[node] + sum_in hs[src]) + b)
// useExt: 1 -> write out_ext (harness d_out), 0 -> write g_buf1.
__global__ __launch_bounds__(256) void k_gather(
    float* __restrict__ out_ext, const float* __restrict__ bias,
    int N, int useExt)
{
    int node = blockIdx.x * 8 + (threadIdx.x >> 5);
    if (node >= N) return;
    int lane = threadIdx.x & 31;
    const float* __restrict__ hs = g_buf0;

    float4 acc = *(const float4*)(hs + (size_t)node * HDIM + lane * 4);
    int beg = g_off[node], end = g_off[node + 1];

    for (int base = beg; base < end; base += 32) {
        int n = end - base; if (n > 32) n = 32;
        int eid = (lane < n) ? g_csr[base + lane] : 0;
        #pragma unroll 8
        for (int j = 0; j < n; j++) {
            int s = __shfl_sync(0xffffffffu, eid, j);
            float4 v = __ldg((const float4*)(hs + (size_t)s * HDIM + lane * 4));
            acc.x += v.x; acc.y += v.y; acc.z += v.z; acc.w += v.w;
        }
    }

    float sc = g_dis[node];
    float4 bb = __ldg((const float4*)(bias + lane * 4));
    float4 r;
    r.x = fmaxf(fmaf(sc, acc.x, bb.x), 0.f);
    r.y = fmaxf(fmaf(sc, acc.y, bb.y), 0.f);
    r.z = fmaxf(fmaf(sc, acc.z, bb.z), 0.f);
    r.w = fmaxf(fmaf(sc, acc.w, bb.w), 0.f);

    float* __restrict__ out = useExt ? out_ext : g_buf1;
    *(float4*)(out + (size_t)node * HDIM + lane * 4) = r;
}

extern "C" void kernel_launch(void* const* d_in, const int* in_sizes, int n_in,
                              void* d_out, int out_size)
{
    const float* x  = (const float*)d_in[0];
    const void*  ei = d_in[1];
    const float* W1 = (const float*)d_in[2];
    const float* b1 = (const float*)d_in[3];
    const float* W2 = (const float*)d_in[4];
    const float* b2 = (const float*)d_in[5];

    int H = in_sizes[3];
    int D = in_sizes[2] / H;
    int N = in_sizes[0] / D;
    int E = in_sizes[1] / 2;
    (void)D; (void)n_in; (void)out_size;

    int nb    = (N + 1023) / 1024;
    int eb    = (E + 255) / 256;
    int nb256 = (N + 255) / 256;

    // probe + degree + normalization + CSR build
    k_detect<<<1, 32>>>(ei, E, N);
    k_init<<<nb256, 256>>>(N);
    k_count<<<eb, 256>>>(ei, E, N);
    k_dis<<<nb256, 256>>>(N);
    k_scan1<<<nb, 256>>>(N);
    k_scan2<<<1, 64>>>(nb);
    k_scan3<<<nb256, 256>>>(N, E);
    k_fill<<<eb, 256>>>(ei, E, N);

    int gemmBlocks = (N + 63) / 64;
    int gathBlocks = (N + 7) / 8;

    // layer 1: hs -> buf0, gathered z -> buf1
    k_gemm_scale<<<gemmBlocks, 256>>>(x, W1, N, 0);
    k_gather<<<gathBlocks, 256>>>(nullptr, b1, N, 0);

    // layer 2: hs -> buf0, gathered z -> d_out
    k_gemm_scale<<<gemmBlocks, 256>>>(nullptr, W2, N, 1);
    k_gather<<<gathBlocks, 256>>>((float*)d_out, b2, N, 1);
}